// round 3
// baseline (speedup 1.0000x reference)
#include <cuda_runtime.h>
#include <cuda_bf16.h>
#include <math.h>

// Problem constants
#define CLOUDS 64
#define PPC    128      // points per cloud
#define DIM    128
#define NNODES (CLOUDS * PPC)   // 8192
#define EPSV   1e-5f

typedef unsigned long long ull;

// ---------------- scratch (device globals; no allocation allowed) -------------
__device__ float g_Y[NNODES * DIM];     // X @ W1
__device__ float g_P2[NNODES * DIM];    // branch-2 pooled
__device__ float g_ps[128 * 128];       // per-CTA partial sums (batchnorm)
__device__ float g_pss[128 * 128];      // per-CTA partial sums of squares
__device__ float g_bstats[256];         // [0:128) scale, [128:256) shift

// ---------------- f32x2 helpers ----------------------------------------------
__device__ __forceinline__ ull pack2(float lo, float hi) {
    ull r; asm("mov.b64 %0, {%1, %2};" : "=l"(r) : "f"(lo), "f"(hi)); return r;
}
__device__ __forceinline__ void unpack2(ull v, float& lo, float& hi) {
    asm("mov.b64 {%0, %1}, %2;" : "=f"(lo), "=f"(hi) : "l"(v));
}
__device__ __forceinline__ ull fma2(ull a, ull b, ull c) {
    ull d; asm("fma.rn.f32x2 %0, %1, %2, %3;" : "=l"(d) : "l"(a), "l"(b), "l"(c)); return d;
}
__device__ __forceinline__ ull add2(ull a, ull b) {
    ull d; asm("add.rn.f32x2 %0, %1, %2;" : "=l"(d) : "l"(a), "l"(b)); return d;
}

#define NEG1_2 0xBF800000BF800000ULL  // (-1.0f, -1.0f)

// ============================================================================
// K0: Y = X @ W1  (fp32, f32x2 packed FMAs). 128 CTAs x 256 threads,
// each CTA computes 64 rows of Y. W1 rows live in smem as packed pairs;
// X is transposed+duplicated in smem so the per-k row scalar is a ready b64.
// ============================================================================
__global__ void __launch_bounds__(256, 1)
k0_gemm(const float* __restrict__ X, const float* __restrict__ W1) {
    extern __shared__ ull sm0[];
    ull* wp = sm0;            // [128 k][64 col-pairs]  == W1 reinterpreted
    ull* xd = sm0 + 8192;     // [128 k][64 rows] duplicated (v,v)

    const int tid = threadIdx.x;
    const int r0  = blockIdx.x * 64;

    // copy W1 (64 KB) into smem
    const float4* w4 = (const float4*)W1;
    float4* wps = (float4*)wp;
    #pragma unroll
    for (int t = 0; t < 16; t++) wps[tid + t * 256] = w4[tid + t * 256];

    // transpose + duplicate X block: xd[k*64 + r] = (x, x)
    #pragma unroll
    for (int t = 0; t < 32; t++) {
        int idx = tid + t * 256;
        int r = idx & 63;
        int k = idx >> 6;
        float v = X[(r0 + r) * DIM + k];
        xd[k * 64 + r] = pack2(v, v);
    }
    __syncthreads();

    const int rb = tid >> 5;   // 8 row-blocks of 8 rows (== warp id -> broadcast LDS)
    const int cb = tid & 31;   // 32 col-blocks of 4 cols (2 pairs)

    ull acc[8][2];
    #pragma unroll
    for (int r = 0; r < 8; r++) { acc[r][0] = 0ULL; acc[r][1] = 0ULL; }

    #pragma unroll 4
    for (int k = 0; k < 128; k++) {
        const ulonglong2* xv = (const ulonglong2*)(xd + k * 64 + rb * 8);
        ulonglong2 x0 = xv[0], x1 = xv[1], x2 = xv[2], x3 = xv[3];
        ull xr[8] = {x0.x, x0.y, x1.x, x1.y, x2.x, x2.y, x3.x, x3.y};
        ulonglong2 wv = *(const ulonglong2*)(wp + k * 64 + cb * 2);
        #pragma unroll
        for (int r = 0; r < 8; r++) {
            acc[r][0] = fma2(xr[r], wv.x, acc[r][0]);
            acc[r][1] = fma2(xr[r], wv.y, acc[r][1]);
        }
    }

    #pragma unroll
    for (int r = 0; r < 8; r++) {
        int row = r0 + rb * 8 + r;
        float a, b, c, d;
        unpack2(acc[r][0], a, b);
        unpack2(acc[r][1], c, d);
        float4 o; o.x = a; o.y = b; o.z = c; o.w = d;
        ((float4*)(g_Y + row * DIM))[cb] = o;
    }
}

// ============================================================================
// K1: branch 1.  p1[i,d] = sum_j relu(w_ij*(y_i[d]-y_j[d]) + b1[d]) - relu(b1[d])
// then per-node LayerNorm and write  out = x + norm(p1)*ln_g + ln_b.
// Grid: 128 CTAs (2 per cloud, 64 nodes each) x 512 threads.
// Thread (warp w, lane): i_local = ((w&1)<<5)|lane, d-chunk = (w>>1)*16.
// ============================================================================
__global__ void __launch_bounds__(512, 1)
k1_branch1(const float* __restrict__ X, const float* __restrict__ XYZ,
           const float* __restrict__ b1, const float* __restrict__ ln_g,
           const float* __restrict__ ln_b, float* __restrict__ out) {
    extern __shared__ float sm1[];
    float* ys    = sm1;            // [128][128] Y of the cloud     (16384 f)
    float* ws    = sm1 + 16384;    // [128 j][64 i] edge weights     (8192 f)  (reused as red[])
    float* xyzs  = sm1 + 24576;    // [128][4] xyz of the cloud      (512 f)
    float* stats = sm1 + 25088;    // [64] mu + [64] inv             (128 f)

    const int tid  = threadIdx.x;
    const int w    = tid >> 5;
    const int lane = tid & 31;
    const int i_l   = ((w & 1) << 5) | lane;  // 0..63
    const int dbase = (w >> 1) << 4;          // 0..112 step 16

    const int cta   = blockIdx.x;
    const int node0 = (cta >> 1) << 7;   // cloud * 128
    const int i0    = (cta & 1) << 6;    // 0 or 64

    // load cloud Y
    {
        const float4* Yv = (const float4*)(g_Y + node0 * DIM);
        float4* ysv = (float4*)ys;
        #pragma unroll
        for (int t = 0; t < 8; t++) ysv[tid + t * 512] = Yv[tid + t * 512];
    }
    if (tid < 128) {
        const float* p = XYZ + (node0 + tid) * 3;
        xyzs[tid * 4 + 0] = p[0];
        xyzs[tid * 4 + 1] = p[1];
        xyzs[tid * 4 + 2] = p[2];
        xyzs[tid * 4 + 3] = 0.f;
    }
    __syncthreads();

    // precompute w matrix: ws[j*64 + i] = exp(-dist(i0+i, j))
    #pragma unroll
    for (int t = 0; t < 16; t++) {
        int idx = tid + t * 512;
        int ii = idx & 63;
        int jj = idx >> 6;
        float dx = xyzs[((i0 + ii) << 2) + 0] - xyzs[(jj << 2) + 0];
        float dy = xyzs[((i0 + ii) << 2) + 1] - xyzs[(jj << 2) + 1];
        float dz = xyzs[((i0 + ii) << 2) + 2] - xyzs[(jj << 2) + 2];
        float d2 = dx * dx + dy * dy + dz * dz;
        ws[(jj << 6) + ii] = expf(-sqrtf(d2));
    }

    // cache y_i and b1 as packed pairs
    ull yi[8], b1p[8];
    {
        const ull* ysu = (const ull*)ys;
        int yoff = (((i0 + i_l) << 7) + dbase) >> 1;
        const ull* b1u = (const ull*)b1;
        int boff = dbase >> 1;
        #pragma unroll
        for (int p = 0; p < 8; p++) { yi[p] = ysu[yoff + p]; b1p[p] = b1u[boff + p]; }
    }
    ull acc[8];
    #pragma unroll
    for (int p = 0; p < 8; p++) acc[p] = 0ULL;
    __syncthreads();

    // ---- main pairwise loop over j ----
    #pragma unroll 2
    for (int j = 0; j < 128; j++) {
        float wv = ws[(j << 6) + i_l];
        ull w2 = pack2(wv, wv);
        const ulonglong2* yj2 = (const ulonglong2*)(ys + (j << 7) + dbase);
        ulonglong2 a0 = yj2[0], a1 = yj2[1], a2 = yj2[2], a3 = yj2[3];
        ull yj[8] = {a0.x, a0.y, a1.x, a1.y, a2.x, a2.y, a3.x, a3.y};
        #pragma unroll
        for (int p = 0; p < 8; p++) {
            ull df = fma2(yj[p], NEG1_2, yi[p]);      // y_i - y_j
            ull t  = fma2(w2, df, b1p[p]);            // w*diff + b1
            float lo, hi;
            unpack2(t, lo, hi);
            lo = fmaxf(lo, 0.f);
            hi = fmaxf(hi, 0.f);
            acc[p] = add2(acc[p], pack2(lo, hi));
        }
    }

    // ---- epilogue: self-edge correction + per-node LayerNorm ----
    float af[16];
    #pragma unroll
    for (int p = 0; p < 8; p++) {
        float lo, hi; unpack2(acc[p], lo, hi);
        float bl, bh; unpack2(b1p[p], bl, bh);
        af[2 * p + 0] = lo - fmaxf(bl, 0.f);     // remove j==i term relu(b1)
        af[2 * p + 1] = hi - fmaxf(bh, 0.f);
    }
    float s = 0.f, ssq = 0.f;
    #pragma unroll
    for (int k = 0; k < 16; k++) { s += af[k]; ssq += af[k] * af[k]; }

    __syncthreads();                 // done reading ws/ys in main loop
    float* red = ws;                 // reuse: red[i][16] partials
    red[i_l * 16 + ((w >> 1) << 1) + 0] = s;
    red[i_l * 16 + ((w >> 1) << 1) + 1] = ssq;
    __syncthreads();

    if (tid < 64) {
        float S = 0.f, SS = 0.f;
        #pragma unroll
        for (int cc = 0; cc < 8; cc++) {
            S  += red[tid * 16 + 2 * cc + 0];
            SS += red[tid * 16 + 2 * cc + 1];
        }
        float mu  = S * (1.f / 128.f);
        float var = SS * (1.f / 128.f) - mu * mu;
        stats[tid]      = mu;
        stats[64 + tid] = 1.f / sqrtf(var + EPSV);
    }
    __syncthreads();

    float mu  = stats[i_l];
    float inv = stats[64 + i_l];
    int gb = ((node0 + i0 + i_l) << 7) + dbase;
    #pragma unroll
    for (int q = 0; q < 4; q++) {
        float4 xv = *(const float4*)(X + gb + q * 4);
        float4 gv = *(const float4*)(ln_g + dbase + q * 4);
        float4 bv = *(const float4*)(ln_b + dbase + q * 4);
        float4 o;
        o.x = xv.x + (af[q * 4 + 0] - mu) * inv * gv.x + bv.x;
        o.y = xv.y + (af[q * 4 + 1] - mu) * inv * gv.y + bv.y;
        o.z = xv.z + (af[q * 4 + 2] - mu) * inv * gv.z + bv.z;
        o.w = xv.w + (af[q * 4 + 3] - mu) * inv * gv.w + bv.w;
        *(float4*)(out + gb + q * 4) = o;
    }
}

// ============================================================================
// K2: branch 2.  p2[i,d] = sum_j relu(z_i[d]-z_j[d]),  z = xyz @ W_xyz
// (computed in-prologue per cloud). Writes g_P2 + per-CTA batchnorm partials.
// Same grid / thread mapping as K1.
// ============================================================================
#define ST_STRIDE 132
__global__ void __launch_bounds__(512, 1)
k2_branch2(const float* __restrict__ XYZ, const float* __restrict__ Wxyz) {
    extern __shared__ float sm2[];
    float* zs   = sm2;                       // [128][128]       (16384 f)
    float* st   = sm2 + 16384;               // [64][132] stage  (8448 f)
    float* xyzs = sm2 + 16384 + 8448;        // [128][4]         (512 f)
    float* wxs  = xyzs + 512;                // [3][128]         (384 f)

    const int tid  = threadIdx.x;
    const int w    = tid >> 5;
    const int lane = tid & 31;
    const int i_l   = ((w & 1) << 5) | lane;
    const int dbase = (w >> 1) << 4;

    const int cta   = blockIdx.x;
    const int node0 = (cta >> 1) << 7;
    const int i0    = (cta & 1) << 6;

    if (tid < 128) {
        const float* p = XYZ + (node0 + tid) * 3;
        xyzs[tid * 4 + 0] = p[0];
        xyzs[tid * 4 + 1] = p[1];
        xyzs[tid * 4 + 2] = p[2];
        xyzs[tid * 4 + 3] = 0.f;
    }
    if (tid < 384) wxs[tid] = Wxyz[tid];
    __syncthreads();

    // z for the whole cloud
    #pragma unroll
    for (int t = 0; t < 32; t++) {
        int idx = tid + t * 512;
        int jn = idx >> 7;
        int d  = idx & 127;
        zs[idx] = xyzs[(jn << 2) + 0] * wxs[d]
                + xyzs[(jn << 2) + 1] * wxs[128 + d]
                + xyzs[(jn << 2) + 2] * wxs[256 + d];
    }
    __syncthreads();

    ull zi[8];
    {
        const ull* zsu = (const ull*)zs;
        int zoff = (((i0 + i_l) << 7) + dbase) >> 1;
        #pragma unroll
        for (int p = 0; p < 8; p++) zi[p] = zsu[zoff + p];
    }
    ull acc[8];
    #pragma unroll
    for (int p = 0; p < 8; p++) acc[p] = 0ULL;

    #pragma unroll 2
    for (int j = 0; j < 128; j++) {
        const ulonglong2* zj2 = (const ulonglong2*)(zs + (j << 7) + dbase);
        ulonglong2 a0 = zj2[0], a1 = zj2[1], a2 = zj2[2], a3 = zj2[3];
        ull zj[8] = {a0.x, a0.y, a1.x, a1.y, a2.x, a2.y, a3.x, a3.y};
        #pragma unroll
        for (int p = 0; p < 8; p++) {
            ull df = fma2(zj[p], NEG1_2, zi[p]);      // z_i - z_j
            float lo, hi;
            unpack2(df, lo, hi);
            lo = fmaxf(lo, 0.f);
            hi = fmaxf(hi, 0.f);
            acc[p] = add2(acc[p], pack2(lo, hi));
        }
    }

    // stage p2 tile into smem (self edge contributes relu(0)=0 -> no correction)
    float af[16];
    #pragma unroll
    for (int p = 0; p < 8; p++) unpack2(acc[p], af[2 * p], af[2 * p + 1]);
    #pragma unroll
    for (int q = 0; q < 4; q++) {
        float4 o;
        o.x = af[q * 4 + 0]; o.y = af[q * 4 + 1];
        o.z = af[q * 4 + 2]; o.w = af[q * 4 + 3];
        *(float4*)(st + i_l * ST_STRIDE + dbase + q * 4) = o;
    }
    __syncthreads();

    // deterministic column reduction (64 nodes of this CTA) -> batchnorm partials
    if (tid < 128) {
        float S = 0.f, SS = 0.f;
        #pragma unroll 8
        for (int i = 0; i < 64; i++) {
            float v = st[i * ST_STRIDE + tid];
            S += v; SS += v * v;
        }
        g_ps[cta * 128 + tid]  = S;
        g_pss[cta * 128 + tid] = SS;
    }
    // coalesced write of p2 to global — this CTA owns 64 nodes = 8192 floats
    const int nb = node0 + i0;
    #pragma unroll
    for (int t = 0; t < 16; t++) {
        int idx = tid + t * 512;     // 0 .. 8191
        int i = idx >> 7;            // 0 .. 63
        int d = idx & 127;
        g_P2[((nb + i) << 7) + d] = st[i * ST_STRIDE + d];
    }
}

// ============================================================================
// K3: reduce 128 CTA partials -> batchnorm scale/shift (1 CTA, deterministic)
// ============================================================================
__global__ void k3_reduce(const float* __restrict__ bn_g, const float* __restrict__ bn_b) {
    int d = threadIdx.x;
    float S = 0.f, SS = 0.f;
    #pragma unroll 8
    for (int c = 0; c < 128; c++) {
        S  += g_ps[c * 128 + d];
        SS += g_pss[c * 128 + d];
    }
    float mu  = S * (1.f / (float)NNODES);
    float var = SS * (1.f / (float)NNODES) - mu * mu;
    float inv = 1.f / sqrtf(var + EPSV);
    float scale = inv * bn_g[d];
    g_bstats[d]       = scale;
    g_bstats[128 + d] = bn_b[d] - mu * scale;
}

// ============================================================================
// K4: out += p2 * scale[d] + shift[d]
// ============================================================================
__global__ void __launch_bounds__(256, 1) k4_bn(float* __restrict__ out) {
    __shared__ float sc[128], sh[128];
    int tid = threadIdx.x;
    if (tid < 128) { sc[tid] = g_bstats[tid]; sh[tid] = g_bstats[128 + tid]; }
    __syncthreads();
    #pragma unroll
    for (int t = 0; t < 8; t++) {
        int v = blockIdx.x * 2048 + tid + t * 256;     // float4 index
        int d = (v & 31) << 2;
        float4 p = ((const float4*)g_P2)[v];
        float4 o = ((float4*)out)[v];
        o.x += p.x * sc[d + 0] + sh[d + 0];
        o.y += p.y * sc[d + 1] + sh[d + 1];
        o.z += p.z * sc[d + 2] + sh[d + 2];
        o.w += p.w * sc[d + 3] + sh[d + 3];
        ((float4*)out)[v] = o;
    }
}

// ============================================================================
extern "C" void kernel_launch(void* const* d_in, const int* in_sizes, int n_in,
                              void* d_out, int out_size) {
    const float* X    = (const float*)d_in[0];
    const float* XYZ  = (const float*)d_in[1];
    const float* Wxyz = (const float*)d_in[2];
    const float* bn_g = (const float*)d_in[3];
    const float* bn_b = (const float*)d_in[4];
    const float* W1   = (const float*)d_in[5];
    const float* b1   = (const float*)d_in[6];
    const float* ln_g = (const float*)d_in[7];
    const float* ln_b = (const float*)d_in[8];
    float* out = (float*)d_out;

    const int smem0 = 16384 * 8;                               // 128 KB
    const int smem1 = (16384 + 8192 + 512 + 128) * 4;          // ~100.9 KB
    const int smem2 = (16384 + 8448 + 512 + 384) * 4;          // ~102.9 KB

    cudaFuncSetAttribute(k0_gemm,    cudaFuncAttributeMaxDynamicSharedMemorySize, smem0);
    cudaFuncSetAttribute(k1_branch1, cudaFuncAttributeMaxDynamicSharedMemorySize, smem1);
    cudaFuncSetAttribute(k2_branch2, cudaFuncAttributeMaxDynamicSharedMemorySize, smem2);

    k0_gemm   <<<128, 256, smem0>>>(X, W1);
    k1_branch1<<<128, 512, smem1>>>(X, XYZ, b1, ln_g, ln_b, out);
    k2_branch2<<<128, 512, smem2>>>(XYZ, Wxyz);
    k3_reduce <<<1, 128>>>(bn_g, bn_b);
    k4_bn     <<<128, 256>>>(out);
}

// round 4
// speedup vs baseline: 1.0715x; 1.0715x over previous
#include <cuda_runtime.h>
#include <cuda_bf16.h>
#include <math.h>

// Problem constants
#define CLOUDS 64
#define PPC    128      // points per cloud
#define DIM    128
#define NNODES (CLOUDS * PPC)   // 8192
#define EPSV   1e-5f

typedef unsigned long long ull;

// ---------------- scratch (device globals; no allocation allowed) -------------
__device__ float g_Y[NNODES * DIM];     // X @ W1
__device__ float g_P2[NNODES * DIM];    // branch-2 pooled
__device__ float g_ps[128 * 128];       // per-CTA partial sums (batchnorm)
__device__ float g_pss[128 * 128];      // per-CTA partial sums of squares

// ---------------- f32x2 helpers ----------------------------------------------
__device__ __forceinline__ ull pack2(float lo, float hi) {
    ull r; asm("mov.b64 %0, {%1, %2};" : "=l"(r) : "f"(lo), "f"(hi)); return r;
}
__device__ __forceinline__ void unpack2(ull v, float& lo, float& hi) {
    asm("mov.b64 {%0, %1}, %2;" : "=f"(lo), "=f"(hi) : "l"(v));
}
__device__ __forceinline__ ull fma2(ull a, ull b, ull c) {
    ull d; asm("fma.rn.f32x2 %0, %1, %2, %3;" : "=l"(d) : "l"(a), "l"(b), "l"(c)); return d;
}
__device__ __forceinline__ ull add2(ull a, ull b) {
    ull d; asm("add.rn.f32x2 %0, %1, %2;" : "=l"(d) : "l"(a), "l"(b)); return d;
}

#define NEG1_2 0xBF800000BF800000ULL  // (-1.0f, -1.0f)

// ============================================================================
// K0: Y = X @ W1  (fp32, f32x2 packed FMAs). 128 CTAs x 256 threads,
// each CTA computes 64 rows of Y.
// ============================================================================
__global__ void __launch_bounds__(256, 1)
k0_gemm(const float* __restrict__ X, const float* __restrict__ W1) {
    extern __shared__ ull sm0[];
    ull* wp = sm0;            // [128 k][64 col-pairs]  == W1 reinterpreted
    ull* xd = sm0 + 8192;     // [128 k][64 rows] duplicated (v,v)

    const int tid = threadIdx.x;
    const int r0  = blockIdx.x * 64;

    // copy W1 (64 KB) into smem
    const float4* w4 = (const float4*)W1;
    float4* wps = (float4*)wp;
    #pragma unroll
    for (int t = 0; t < 16; t++) wps[tid + t * 256] = w4[tid + t * 256];

    // transpose + duplicate X block: xd[k*64 + r] = (x, x)
    #pragma unroll
    for (int t = 0; t < 32; t++) {
        int idx = tid + t * 256;
        int r = idx & 63;
        int k = idx >> 6;
        float v = X[(r0 + r) * DIM + k];
        xd[k * 64 + r] = pack2(v, v);
    }
    __syncthreads();

    const int rb = tid >> 5;   // 8 row-blocks of 8 rows
    const int cb = tid & 31;   // 32 col-blocks of 4 cols (2 pairs)

    ull acc[8][2];
    #pragma unroll
    for (int r = 0; r < 8; r++) { acc[r][0] = 0ULL; acc[r][1] = 0ULL; }

    #pragma unroll 4
    for (int k = 0; k < 128; k++) {
        const ulonglong2* xv = (const ulonglong2*)(xd + k * 64 + rb * 8);
        ulonglong2 x0 = xv[0], x1 = xv[1], x2 = xv[2], x3 = xv[3];
        ull xr[8] = {x0.x, x0.y, x1.x, x1.y, x2.x, x2.y, x3.x, x3.y};
        ulonglong2 wv = *(const ulonglong2*)(wp + k * 64 + cb * 2);
        #pragma unroll
        for (int r = 0; r < 8; r++) {
            acc[r][0] = fma2(xr[r], wv.x, acc[r][0]);
            acc[r][1] = fma2(xr[r], wv.y, acc[r][1]);
        }
    }

    #pragma unroll
    for (int r = 0; r < 8; r++) {
        int row = r0 + rb * 8 + r;
        float a, b, c, d;
        unpack2(acc[r][0], a, b);
        unpack2(acc[r][1], c, d);
        float4 o; o.x = a; o.y = b; o.z = c; o.w = d;
        ((float4*)(g_Y + row * DIM))[cb] = o;
    }
}

// ============================================================================
// K1: branch 1.  p1[i,d] = sum_j relu(w_ij*(y_i[d]-y_j[d]) + b1[d]) - relu(b1[d])
// then per-node LayerNorm and write  out = x + norm(p1)*ln_g + ln_b.
// Grid: 128 CTAs (2 per cloud, 64 nodes each) x 512 threads.
// ============================================================================
__global__ void __launch_bounds__(512, 1)
k1_branch1(const float* __restrict__ X, const float* __restrict__ XYZ,
           const float* __restrict__ b1, const float* __restrict__ ln_g,
           const float* __restrict__ ln_b, float* __restrict__ out) {
    extern __shared__ float sm1[];
    float* ys    = sm1;            // [128][128] Y of the cloud     (16384 f)
    float* ws    = sm1 + 16384;    // [128 j][64 i] edge weights     (8192 f)  (reused as red[])
    float* xyzs  = sm1 + 24576;    // [128][4] xyz of the cloud      (512 f)
    float* stats = sm1 + 25088;    // [64] mu + [64] inv             (128 f)

    const int tid  = threadIdx.x;
    const int w    = tid >> 5;
    const int lane = tid & 31;
    const int i_l   = ((w & 1) << 5) | lane;  // 0..63
    const int dbase = (w >> 1) << 4;          // 0..112 step 16

    const int cta   = blockIdx.x;
    const int node0 = (cta >> 1) << 7;   // cloud * 128
    const int i0    = (cta & 1) << 6;    // 0 or 64

    // load cloud Y
    {
        const float4* Yv = (const float4*)(g_Y + node0 * DIM);
        float4* ysv = (float4*)ys;
        #pragma unroll
        for (int t = 0; t < 8; t++) ysv[tid + t * 512] = Yv[tid + t * 512];
    }
    if (tid < 128) {
        const float* p = XYZ + (node0 + tid) * 3;
        xyzs[tid * 4 + 0] = p[0];
        xyzs[tid * 4 + 1] = p[1];
        xyzs[tid * 4 + 2] = p[2];
        xyzs[tid * 4 + 3] = 0.f;
    }
    __syncthreads();

    // precompute w matrix: ws[j*64 + i] = exp(-dist(i0+i, j))
    #pragma unroll
    for (int t = 0; t < 16; t++) {
        int idx = tid + t * 512;
        int ii = idx & 63;
        int jj = idx >> 6;
        float dx = xyzs[((i0 + ii) << 2) + 0] - xyzs[(jj << 2) + 0];
        float dy = xyzs[((i0 + ii) << 2) + 1] - xyzs[(jj << 2) + 1];
        float dz = xyzs[((i0 + ii) << 2) + 2] - xyzs[(jj << 2) + 2];
        float d2 = dx * dx + dy * dy + dz * dz;
        ws[(jj << 6) + ii] = expf(-sqrtf(d2));
    }

    // cache y_i and b1 as packed pairs
    ull yi[8], b1p[8];
    {
        const ull* ysu = (const ull*)ys;
        int yoff = (((i0 + i_l) << 7) + dbase) >> 1;
        const ull* b1u = (const ull*)b1;
        int boff = dbase >> 1;
        #pragma unroll
        for (int p = 0; p < 8; p++) { yi[p] = ysu[yoff + p]; b1p[p] = b1u[boff + p]; }
    }
    ull acc[8];
    #pragma unroll
    for (int p = 0; p < 8; p++) acc[p] = 0ULL;
    __syncthreads();

    // ---- main pairwise loop over j ----
    #pragma unroll 2
    for (int j = 0; j < 128; j++) {
        float wv = ws[(j << 6) + i_l];
        ull w2 = pack2(wv, wv);
        const ulonglong2* yj2 = (const ulonglong2*)(ys + (j << 7) + dbase);
        ulonglong2 a0 = yj2[0], a1 = yj2[1], a2 = yj2[2], a3 = yj2[3];
        ull yj[8] = {a0.x, a0.y, a1.x, a1.y, a2.x, a2.y, a3.x, a3.y};
        #pragma unroll
        for (int p = 0; p < 8; p++) {
            ull df = fma2(yj[p], NEG1_2, yi[p]);      // y_i - y_j
            ull t  = fma2(w2, df, b1p[p]);            // w*diff + b1
            float lo, hi;
            unpack2(t, lo, hi);
            lo = fmaxf(lo, 0.f);
            hi = fmaxf(hi, 0.f);
            acc[p] = add2(acc[p], pack2(lo, hi));
        }
    }

    // ---- epilogue: self-edge correction + per-node LayerNorm ----
    float af[16];
    #pragma unroll
    for (int p = 0; p < 8; p++) {
        float lo, hi; unpack2(acc[p], lo, hi);
        float bl, bh; unpack2(b1p[p], bl, bh);
        af[2 * p + 0] = lo - fmaxf(bl, 0.f);     // remove j==i term relu(b1)
        af[2 * p + 1] = hi - fmaxf(bh, 0.f);
    }
    float s = 0.f, ssq = 0.f;
    #pragma unroll
    for (int k = 0; k < 16; k++) { s += af[k]; ssq += af[k] * af[k]; }

    __syncthreads();                 // done reading ws/ys in main loop
    float* red = ws;                 // reuse: red[i][16] partials
    red[i_l * 16 + ((w >> 1) << 1) + 0] = s;
    red[i_l * 16 + ((w >> 1) << 1) + 1] = ssq;
    __syncthreads();

    if (tid < 64) {
        float S = 0.f, SS = 0.f;
        #pragma unroll
        for (int cc = 0; cc < 8; cc++) {
            S  += red[tid * 16 + 2 * cc + 0];
            SS += red[tid * 16 + 2 * cc + 1];
        }
        float mu  = S * (1.f / 128.f);
        float var = SS * (1.f / 128.f) - mu * mu;
        stats[tid]      = mu;
        stats[64 + tid] = 1.f / sqrtf(var + EPSV);
    }
    __syncthreads();

    float mu  = stats[i_l];
    float inv = stats[64 + i_l];
    int gb = ((node0 + i0 + i_l) << 7) + dbase;
    #pragma unroll
    for (int q = 0; q < 4; q++) {
        float4 xv = *(const float4*)(X + gb + q * 4);
        float4 gv = *(const float4*)(ln_g + dbase + q * 4);
        float4 bv = *(const float4*)(ln_b + dbase + q * 4);
        float4 o;
        o.x = xv.x + (af[q * 4 + 0] - mu) * inv * gv.x + bv.x;
        o.y = xv.y + (af[q * 4 + 1] - mu) * inv * gv.y + bv.y;
        o.z = xv.z + (af[q * 4 + 2] - mu) * inv * gv.z + bv.z;
        o.w = xv.w + (af[q * 4 + 3] - mu) * inv * gv.w + bv.w;
        *(float4*)(out + gb + q * 4) = o;
    }
}

// ============================================================================
// K2: branch 2.  p2[i,d] = sum_j relu(z_i[d]-z_j[d]),  z = xyz @ W_xyz.
// Writes g_P2 + per-CTA batchnorm partials.
// ============================================================================
#define ST_STRIDE 132
__global__ void __launch_bounds__(512, 1)
k2_branch2(const float* __restrict__ XYZ, const float* __restrict__ Wxyz) {
    extern __shared__ float sm2[];
    float* zs   = sm2;                       // [128][128]       (16384 f)
    float* st   = sm2 + 16384;               // [64][132] stage  (8448 f)
    float* xyzs = sm2 + 16384 + 8448;        // [128][4]         (512 f)
    float* wxs  = xyzs + 512;                // [3][128]         (384 f)

    const int tid  = threadIdx.x;
    const int w    = tid >> 5;
    const int lane = tid & 31;
    const int i_l   = ((w & 1) << 5) | lane;
    const int dbase = (w >> 1) << 4;

    const int cta   = blockIdx.x;
    const int node0 = (cta >> 1) << 7;
    const int i0    = (cta & 1) << 6;

    if (tid < 128) {
        const float* p = XYZ + (node0 + tid) * 3;
        xyzs[tid * 4 + 0] = p[0];
        xyzs[tid * 4 + 1] = p[1];
        xyzs[tid * 4 + 2] = p[2];
        xyzs[tid * 4 + 3] = 0.f;
    }
    if (tid < 384) wxs[tid] = Wxyz[tid];
    __syncthreads();

    // z for the whole cloud
    #pragma unroll
    for (int t = 0; t < 32; t++) {
        int idx = tid + t * 512;
        int jn = idx >> 7;
        int d  = idx & 127;
        zs[idx] = xyzs[(jn << 2) + 0] * wxs[d]
                + xyzs[(jn << 2) + 1] * wxs[128 + d]
                + xyzs[(jn << 2) + 2] * wxs[256 + d];
    }
    __syncthreads();

    ull zi[8];
    {
        const ull* zsu = (const ull*)zs;
        int zoff = (((i0 + i_l) << 7) + dbase) >> 1;
        #pragma unroll
        for (int p = 0; p < 8; p++) zi[p] = zsu[zoff + p];
    }
    ull acc[8];
    #pragma unroll
    for (int p = 0; p < 8; p++) acc[p] = 0ULL;

    #pragma unroll 2
    for (int j = 0; j < 128; j++) {
        const ulonglong2* zj2 = (const ulonglong2*)(zs + (j << 7) + dbase);
        ulonglong2 a0 = zj2[0], a1 = zj2[1], a2 = zj2[2], a3 = zj2[3];
        ull zj[8] = {a0.x, a0.y, a1.x, a1.y, a2.x, a2.y, a3.x, a3.y};
        #pragma unroll
        for (int p = 0; p < 8; p++) {
            ull df = fma2(zj[p], NEG1_2, zi[p]);      // z_i - z_j
            float lo, hi;
            unpack2(df, lo, hi);
            lo = fmaxf(lo, 0.f);
            hi = fmaxf(hi, 0.f);
            acc[p] = add2(acc[p], pack2(lo, hi));
        }
    }

    // stage p2 tile into smem (self edge contributes relu(0)=0 -> no correction)
    float af[16];
    #pragma unroll
    for (int p = 0; p < 8; p++) unpack2(acc[p], af[2 * p], af[2 * p + 1]);
    #pragma unroll
    for (int q = 0; q < 4; q++) {
        float4 o;
        o.x = af[q * 4 + 0]; o.y = af[q * 4 + 1];
        o.z = af[q * 4 + 2]; o.w = af[q * 4 + 3];
        *(float4*)(st + i_l * ST_STRIDE + dbase + q * 4) = o;
    }
    __syncthreads();

    // deterministic column reduction (64 nodes of this CTA) -> batchnorm partials
    if (tid < 128) {
        float S = 0.f, SS = 0.f;
        #pragma unroll 8
        for (int i = 0; i < 64; i++) {
            float v = st[i * ST_STRIDE + tid];
            S += v; SS += v * v;
        }
        g_ps[cta * 128 + tid]  = S;
        g_pss[cta * 128 + tid] = SS;
    }
    // coalesced write of p2 to global — this CTA owns 64 nodes = 8192 floats
    const int nb = node0 + i0;
    #pragma unroll
    for (int t = 0; t < 16; t++) {
        int idx = tid + t * 512;     // 0 .. 8191
        int i = idx >> 7;            // 0 .. 63
        int d = idx & 127;
        g_P2[((nb + i) << 7) + d] = st[i * ST_STRIDE + d];
    }
}

// ============================================================================
// K34: fused batchnorm stats + apply.
// Every CTA redundantly reduces the 128-KB partial arrays (L2-resident,
// 256 threads x 128 independent strided loads -> ~2K cycles), computes
// scale/shift once in smem, then applies:  out += p2 * scale[d] + shift[d].
// Deterministic: fixed two-half summation order.
// ============================================================================
__global__ void __launch_bounds__(256, 1)
k34_bn(const float* __restrict__ bn_g, const float* __restrict__ bn_b,
       float* __restrict__ out) {
    __shared__ float sS[256], sSS[256];
    __shared__ float sc[128], sh[128];
    const int tid  = threadIdx.x;
    const int d    = tid & 127;
    const int half = tid >> 7;           // 0 or 1

    // ---- stats prologue: thread sums 64 CTA-partials (one half) for its d ----
    const float* ps  = g_ps  + half * 64 * 128 + d;
    const float* pss = g_pss + half * 64 * 128 + d;
    float S = 0.f, SS = 0.f;
    #pragma unroll 16
    for (int c = 0; c < 64; c++) {
        S  += ps[c * 128];
        SS += pss[c * 128];
    }
    sS[tid] = S; sSS[tid] = SS;
    __syncthreads();
    if (tid < 128) {
        float St  = sS[tid]  + sS[tid + 128];
        float SSt = sSS[tid] + sSS[tid + 128];
        float mu  = St * (1.f / (float)NNODES);
        float var = SSt * (1.f / (float)NNODES) - mu * mu;
        float inv = 1.f / sqrtf(var + EPSV);
        float scale = inv * bn_g[tid];
        sc[tid] = scale;
        sh[tid] = bn_b[tid] - mu * scale;
    }
    __syncthreads();

    // ---- apply ----
    #pragma unroll
    for (int t = 0; t < 8; t++) {
        int v = blockIdx.x * 2048 + tid + t * 256;     // float4 index
        int dd = (v & 31) << 2;
        float4 p = ((const float4*)g_P2)[v];
        float4 o = ((float4*)out)[v];
        o.x += p.x * sc[dd + 0] + sh[dd + 0];
        o.y += p.y * sc[dd + 1] + sh[dd + 1];
        o.z += p.z * sc[dd + 2] + sh[dd + 2];
        o.w += p.w * sc[dd + 3] + sh[dd + 3];
        ((float4*)out)[v] = o;
    }
}

// ============================================================================
extern "C" void kernel_launch(void* const* d_in, const int* in_sizes, int n_in,
                              void* d_out, int out_size) {
    const float* X    = (const float*)d_in[0];
    const float* XYZ  = (const float*)d_in[1];
    const float* Wxyz = (const float*)d_in[2];
    const float* bn_g = (const float*)d_in[3];
    const float* bn_b = (const float*)d_in[4];
    const float* W1   = (const float*)d_in[5];
    const float* b1   = (const float*)d_in[6];
    const float* ln_g = (const float*)d_in[7];
    const float* ln_b = (const float*)d_in[8];
    float* out = (float*)d_out;

    const int smem0 = 16384 * 8;                               // 128 KB
    const int smem1 = (16384 + 8192 + 512 + 128) * 4;          // ~100.9 KB
    const int smem2 = (16384 + 8448 + 512 + 384) * 4;          // ~102.9 KB

    cudaFuncSetAttribute(k0_gemm,    cudaFuncAttributeMaxDynamicSharedMemorySize, smem0);
    cudaFuncSetAttribute(k1_branch1, cudaFuncAttributeMaxDynamicSharedMemorySize, smem1);
    cudaFuncSetAttribute(k2_branch2, cudaFuncAttributeMaxDynamicSharedMemorySize, smem2);

    k0_gemm   <<<128, 256, smem0>>>(X, W1);
    k2_branch2<<<128, 512, smem2>>>(XYZ, Wxyz);
    k1_branch1<<<128, 512, smem1>>>(X, XYZ, b1, ln_g, ln_b, out);
    k34_bn    <<<128, 256>>>(bn_g, bn_b, out);
}